// round 2
// baseline (speedup 1.0000x reference)
#include <cuda_runtime.h>
#include <cstdint>

#define NB   16
#define NN   25200
#define NCLS 80
#define CAP  1024
#define MAXDET 300
#define CONF_T 0.25f
#define IOU_T  0.45f
#define MAXWH  4096.0f

// ---------------- scratch (device globals: no runtime allocation) ----------------
__device__ int                g_bcnt[NB * NCLS];
__device__ unsigned long long g_bkeys[(size_t)NB * NCLS * CAP];   // candidate keys per bucket
__device__ int                g_kcnt[NB * NCLS];
__device__ unsigned long long g_kkeys[(size_t)NB * NCLS * CAP];   // kept keys per bucket (sorted desc)

// key = (float_bits(score) << 32) | (0xFFFFFFFF - n)
// score > 0.25 so bits > 0 -> key != 0; larger key == higher score, tie -> smaller n.

__global__ void k_init() {
    int i = blockIdx.x * blockDim.x + threadIdx.x;
    if (i < NB * NCLS) { g_bcnt[i] = 0; g_kcnt[i] = 0; }
}

// ---------------- 1) decode + bucket ----------------
__global__ void k_decode(const float* __restrict__ pred) {
    int i = blockIdx.x * blockDim.x + threadIdx.x;
    if (i >= NB * NN) return;
    const float* p = pred + (size_t)i * 85;
    float obj = p[4];
    float best = -1.0f;
    int   j = 0;
    #pragma unroll 8
    for (int k = 0; k < NCLS; k++) {
        float v = p[5 + k] * obj;          // exact reference arithmetic
        if (v > best) { best = v; j = k; } // first-max tie-break (strict >)
    }
    if (obj > CONF_T && best > CONF_T) {
        int b = i / NN;
        unsigned n = (unsigned)(i % NN);
        int bucket = b * NCLS + j;
        int pos = atomicAdd(&g_bcnt[bucket], 1);
        if (pos < CAP) {
            unsigned long long key =
                ((unsigned long long)__float_as_uint(best) << 32) |
                (unsigned long long)(0xFFFFFFFFu - n);
            g_bkeys[(size_t)bucket * CAP + pos] = key;
        }
    }
}

// ---------------- 2) per-bucket sort + greedy NMS ----------------
__global__ __launch_bounds__(256) void k_nms(const float* __restrict__ pred) {
    __shared__ unsigned long long sk[CAP];
    __shared__ float sx0[CAP], sy0[CAP], sx1[CAP], sy1[CAP], sa[CAP];
    __shared__ unsigned char sup[CAP];

    int bucket = blockIdx.x;
    int b = bucket / NCLS;
    int c = bucket % NCLS;
    int tid = threadIdx.x;

    int cnt = g_bcnt[bucket];
    if (cnt > CAP) cnt = CAP;

    for (int t = tid; t < CAP; t += 256)
        sk[t] = (t < cnt) ? g_bkeys[(size_t)bucket * CAP + t] : 0ULL;
    __syncthreads();

    if (cnt > 1) {
        // bitonic sort 1024 keys, descending
        for (int k = 2; k <= CAP; k <<= 1) {
            for (int j = k >> 1; j > 0; j >>= 1) {
                for (int t = tid; t < CAP; t += 256) {
                    int p = t ^ j;
                    if (p > t) {
                        bool up = ((t & k) == 0);
                        unsigned long long a = sk[t], bb = sk[p];
                        if ((a < bb) == up) { sk[t] = bb; sk[p] = a; }
                    }
                }
                __syncthreads();
            }
        }
    }

    // load boxes (offset coords, exact reference op order)
    float off = (float)c * MAXWH;
    for (int t = tid; t < cnt; t += 256) {
        unsigned n = 0xFFFFFFFFu - (unsigned)(sk[t] & 0xFFFFFFFFu);
        const float* p = pred + ((size_t)b * NN + n) * 85;
        float cx = p[0], cy = p[1], w = p[2], h = p[3];
        float x0 = cx - w * 0.5f, y0 = cy - h * 0.5f;
        float x1 = cx + w * 0.5f, y1 = cy + h * 0.5f;
        x0 += off; y0 += off; x1 += off; y1 += off;
        sx0[t] = x0; sy0[t] = y0; sx1[t] = x1; sy1[t] = y1;
        sa[t]  = (x1 - x0) * (y1 - y0);
        sup[t] = 0;
    }
    __syncthreads();

    int kept = 0;
    for (int i = 0; i < cnt; i++) {
        __syncthreads();
        if (sup[i]) continue;               // uniform branch
        if (tid == 0)
            g_kkeys[(size_t)bucket * CAP + kept] = sk[i];
        kept++;
        float bx0 = sx0[i], by0 = sy0[i], bx1 = sx1[i], by1 = sy1[i], ba = sa[i];
        for (int t = i + 1 + tid; t < cnt; t += 256) {
            float ltx = fmaxf(bx0, sx0[t]);
            float lty = fmaxf(by0, sy0[t]);
            float rbx = fminf(bx1, sx1[t]);
            float rby = fminf(by1, sy1[t]);
            float iw = fmaxf(rbx - ltx, 0.0f);
            float ih = fmaxf(rby - lty, 0.0f);
            float inter = iw * ih;
            float iou = inter / (((ba + sa[t]) - inter) + 1e-9f);
            if (iou > IOU_T) sup[t] = 1;
        }
    }
    if (tid == 0) g_kcnt[bucket] = kept;
}

// ---------------- 3) per-image 80-way merge + output ----------------
__global__ __launch_bounds__(256) void k_merge(const float* __restrict__ pred,
                                               const float* __restrict__ logits,
                                               float* __restrict__ out) {
    int b = blockIdx.x;
    int tid = threadIdx.x;
    __shared__ unsigned long long selK[MAXDET];
    __shared__ int selC[MAXDET];
    __shared__ int s_tsel;

    if (tid < 32) {
        int lane = tid;
        unsigned long long hk[3];
        int hp[3], hcn[3];
        int nl = (lane < 16) ? 3 : 2;
        #pragma unroll
        for (int s = 0; s < 3; s++) { hk[s] = 0ULL; hp[s] = 0; hcn[s] = 0; }
        for (int s = 0; s < nl; s++) {
            int c = lane + 32 * s;
            int cnt = g_kcnt[b * NCLS + c];
            hcn[s] = cnt;
            hk[s] = (cnt > 0) ? g_kkeys[((size_t)(b * NCLS + c)) * CAP] : 0ULL;
        }
        int tsel = MAXDET;
        for (int t = 0; t < MAXDET; t++) {
            unsigned long long lb = 0ULL; int ls = -1;
            #pragma unroll
            for (int s = 0; s < 3; s++)
                if (hk[s] > lb) { lb = hk[s]; ls = s; }
            unsigned long long wk = lb;
            #pragma unroll
            for (int o = 16; o > 0; o >>= 1) {
                unsigned long long other = __shfl_down_sync(0xffffffffu, wk, o);
                if (other > wk) wk = other;
            }
            wk = __shfl_sync(0xffffffffu, wk, 0);
            if (wk == 0ULL) { tsel = t; break; }
            if (lb == wk && ls >= 0) {         // unique key -> exactly one lane
                selK[t] = wk;
                selC[t] = lane + 32 * ls;
                hp[ls]++;
                hk[ls] = (hp[ls] < hcn[ls])
                    ? g_kkeys[((size_t)(b * NCLS + lane + 32 * ls)) * CAP + hp[ls]]
                    : 0ULL;
            }
        }
        if (lane == 0) s_tsel = tsel;
    }
    __syncthreads();
    int tsel = s_tsel;

    float* dets  = out;                               // [16,300,6]
    float* lg    = out + (size_t)NB * MAXDET * 6;     // [16,300,80]
    float* keepo = out + (size_t)NB * MAXDET * 86;    // [16,300]

    for (int r = tid; r < MAXDET; r += blockDim.x) {
        float d0 = 0, d1 = 0, d2 = 0, d3 = 0, d4 = 0, d5 = 0, kf = 0;
        if (r < tsel) {
            unsigned long long key = selK[r];
            unsigned n = 0xFFFFFFFFu - (unsigned)(key & 0xFFFFFFFFu);
            float conf = __uint_as_float((unsigned)(key >> 32));
            const float* p = pred + ((size_t)b * NN + n) * 85;
            float cx = p[0], cy = p[1], w = p[2], h = p[3];
            d0 = cx - w * 0.5f; d1 = cy - h * 0.5f;
            d2 = cx + w * 0.5f; d3 = cy + h * 0.5f;
            d4 = conf; d5 = (float)selC[r]; kf = 1.0f;
        }
        float* dr = dets + ((size_t)b * MAXDET + r) * 6;
        dr[0] = d0; dr[1] = d1; dr[2] = d2; dr[3] = d3; dr[4] = d4; dr[5] = d5;
        keepo[(size_t)b * MAXDET + r] = kf;
    }
    for (int idx = tid; idx < MAXDET * NCLS; idx += blockDim.x) {
        int r = idx / NCLS, col = idx % NCLS;
        float v = 0.0f;
        if (r < tsel) {
            unsigned n = 0xFFFFFFFFu - (unsigned)(selK[r] & 0xFFFFFFFFu);
            v = logits[((size_t)b * NN + n) * NCLS + col];
        }
        lg[((size_t)b * MAXDET + r) * NCLS + col] = v;
    }
}

extern "C" void kernel_launch(void* const* d_in, const int* in_sizes, int n_in,
                              void* d_out, int out_size) {
    const float* pred;
    const float* logits;
    // prediction has 16*25200*85 elements, logits 16*25200*80
    if (in_sizes[0] == NB * NN * 85) {
        pred = (const float*)d_in[0];
        logits = (const float*)d_in[1];
    } else {
        pred = (const float*)d_in[1];
        logits = (const float*)d_in[0];
    }
    float* out = (float*)d_out;

    k_init<<<(NB * NCLS + 255) / 256, 256>>>();
    k_decode<<<(NB * NN + 255) / 256, 256>>>(pred);
    k_nms<<<NB * NCLS, 256>>>(pred);
    k_merge<<<NB, 256>>>(pred, logits, out);
}